// round 1
// baseline (speedup 1.0000x reference)
#include <cuda_runtime.h>
#include <cuda_bf16.h>
#include <cstdint>

// ---------------- problem constants ----------------
#define NN      10000
#define EE      320000
#define D_IN    128
#define HH      128
#define LL      3
#define D_CAT   256      // D_IN + H
#define WH      256      // 2*H
#define D_OUT   128
#define LN_EPS  1e-5f
#define SLOPE   0.1f

// ---------------- scratch (no allocation allowed) ----------------
__device__ float g_HID[NN * 512];   // [h0 | h1 | h2 | h3]
__device__ float g_Z  [NN * D_CAT]; // xc + agg
__device__ float g_T1 [NN * WH];
__device__ float g_T2 [NN * WH];
__device__ int   g_is_i64;

// ---------------- edge-index dtype detection ----------------
// If the buffer holds int64 little-endian indices in [0,10000), every odd
// 32-bit word is 0. If it holds random int32 indices, that is (practically)
// never true for 1024 consecutive slots.
__global__ void detect_kernel(const unsigned int* __restrict__ w) {
    __shared__ int bad;
    if (threadIdx.x == 0) bad = 0;
    __syncthreads();
    unsigned int v = w[2 * threadIdx.x + 1];
    if (v != 0u) atomicExch(&bad, 1);
    __syncthreads();
    if (threadIdx.x == 0) g_is_i64 = (bad == 0) ? 1 : 0;
}

// ---------------- Z init: Z[n] = concat(x[n], h_l[n]) ----------------
__global__ void init_z_kernel(const float* __restrict__ x, int hid_off) {
    int i = blockIdx.x * blockDim.x + threadIdx.x;     // float4 index, N*64 total
    if (i >= NN * 64) return;
    int n  = i >> 6;
    int d4 = (i & 63) * 4;
    float4 v;
    if (d4 < 128) v = *(const float4*)(x + (size_t)n * D_IN + d4);
    else          v = *(const float4*)(g_HID + (size_t)n * 512 + hid_off + (d4 - 128));
    *(float4*)(g_Z + (size_t)n * D_CAT + d4) = v;
}

// ---------------- edge kernel: Z[dst] += relu(xc[src] + ea*eW + eB) ----------------
// 64 threads per edge, 4 floats per thread.
__global__ void edge_kernel(const void* __restrict__ ei,
                            const float* __restrict__ ea,
                            const float* __restrict__ eWl,
                            const float* __restrict__ eBl,
                            const float* __restrict__ x,
                            int hid_off) {
    int e = blockIdx.x * 4 + (threadIdx.x >> 6);
    if (e >= EE) return;
    int lane = threadIdx.x & 63;
    int d = lane * 4;

    long long src, dst;
    if (g_is_i64) {
        src = ((const long long*)ei)[e];
        dst = ((const long long*)ei)[EE + e];
    } else {
        src = ((const int*)ei)[e];
        dst = ((const int*)ei)[EE + e];
    }
    float a = __ldg(ea + e);

    float4 xv;
    if (d < 128) xv = *(const float4*)(x + (size_t)src * D_IN + d);
    else         xv = *(const float4*)(g_HID + (size_t)src * 512 + hid_off + (d - 128));

    float4 w  = *(const float4*)(eWl + d);
    float4 bb = *(const float4*)(eBl + d);

    float m0 = fmaxf(xv.x + fmaf(a, w.x, bb.x), 0.0f);
    float m1 = fmaxf(xv.y + fmaf(a, w.y, bb.y), 0.0f);
    float m2 = fmaxf(xv.z + fmaf(a, w.z, bb.z), 0.0f);
    float m3 = fmaxf(xv.w + fmaf(a, w.w, bb.w), 0.0f);

    float* zp = g_Z + (size_t)dst * D_CAT + d;
    atomicAdd(zp + 0, m0);
    atomicAdd(zp + 1, m1);
    atomicAdd(zp + 2, m2);
    atomicAdd(zp + 3, m3);
}

// ---------------- LayerNorm + LeakyReLU (row of 256) ----------------
__global__ void ln_leaky_kernel(float* __restrict__ T,
                                const float* __restrict__ g,
                                const float* __restrict__ b) {
    int row = blockIdx.x;
    int tid = threadIdx.x;                      // 256 threads
    float v = T[(size_t)row * WH + tid];

    float s = v, s2 = v * v;
    #pragma unroll
    for (int off = 16; off > 0; off >>= 1) {
        s  += __shfl_down_sync(0xffffffffu, s,  off);
        s2 += __shfl_down_sync(0xffffffffu, s2, off);
    }
    __shared__ float sh_s[8], sh_s2[8];
    int wid = tid >> 5, lid = tid & 31;
    if (lid == 0) { sh_s[wid] = s; sh_s2[wid] = s2; }
    __syncthreads();
    __shared__ float sh_mu, sh_rstd;
    if (tid == 0) {
        float ts = 0.f, ts2 = 0.f;
        #pragma unroll
        for (int i = 0; i < 8; i++) { ts += sh_s[i]; ts2 += sh_s2[i]; }
        float mu  = ts * (1.0f / WH);
        float var = ts2 * (1.0f / WH) - mu * mu;
        sh_mu = mu;
        sh_rstd = rsqrtf(var + LN_EPS);
    }
    __syncthreads();
    float y = (v - sh_mu) * sh_rstd * g[tid] + b[tid];
    T[(size_t)row * WH + tid] = (y > 0.f) ? y : SLOPE * y;
}

// ---------------- fp32 tiled GEMM:  C = A @ B + bias [, leaky] ----------------
// A: [M,K] row-major (lda), B: [K,N] row-major (ldb), C row-major (ldc).
// N must be a multiple of BN, K a multiple of BK. M is guarded.
template <int BM, int BN, int BK, int TM, int TN, bool LEAKY>
__global__ void sgemm_kernel(int M, int N, int K,
                             const float* __restrict__ A, int lda,
                             const float* __restrict__ B, int ldb,
                             const float* __restrict__ bias,
                             float* __restrict__ C, int ldc) {
    constexpr int THREADS = (BM / TM) * (BN / TN);   // 256
    __shared__ float As[BK][BM + 4];
    __shared__ float Bs[BK][BN + 4];

    const int tid  = threadIdx.x;
    const int tcol = tid % (BN / TN);
    const int trow = tid / (BN / TN);
    const int brow = blockIdx.x * BM;
    const int bcol = blockIdx.y * BN;

    float acc[TM][TN];
    #pragma unroll
    for (int i = 0; i < TM; i++)
        #pragma unroll
        for (int j = 0; j < TN; j++) acc[i][j] = 0.f;

    constexpr int A_LOADS = BM * BK / 4 / THREADS;
    constexpr int B_LOADS = BK * BN / 4 / THREADS;

    for (int k0 = 0; k0 < K; k0 += BK) {
        #pragma unroll
        for (int i = 0; i < A_LOADS; i++) {
            int idx = tid + i * THREADS;
            int r   = idx / (BK / 4);
            int c4  = (idx % (BK / 4)) * 4;
            int gr  = brow + r;
            float4 v = make_float4(0.f, 0.f, 0.f, 0.f);
            if (gr < M) v = *(const float4*)(A + (size_t)gr * lda + k0 + c4);
            As[c4 + 0][r] = v.x;
            As[c4 + 1][r] = v.y;
            As[c4 + 2][r] = v.z;
            As[c4 + 3][r] = v.w;
        }
        #pragma unroll
        for (int i = 0; i < B_LOADS; i++) {
            int idx = tid + i * THREADS;
            int r   = idx / (BN / 4);
            int c4  = (idx % (BN / 4)) * 4;
            *(float4*)&Bs[r][c4] = *(const float4*)(B + (size_t)(k0 + r) * ldb + bcol + c4);
        }
        __syncthreads();

        #pragma unroll
        for (int kk = 0; kk < BK; kk++) {
            float a[TM], bv[TN];
            #pragma unroll
            for (int i = 0; i < TM; i += 4)
                *(float4*)&a[i] = *(const float4*)&As[kk][trow * TM + i];
            #pragma unroll
            for (int j = 0; j < TN; j += 4)
                *(float4*)&bv[j] = *(const float4*)&Bs[kk][tcol * TN + j];
            #pragma unroll
            for (int i = 0; i < TM; i++)
                #pragma unroll
                for (int j = 0; j < TN; j++)
                    acc[i][j] = fmaf(a[i], bv[j], acc[i][j]);
        }
        __syncthreads();
    }

    #pragma unroll
    for (int i = 0; i < TM; i++) {
        int gr = brow + trow * TM + i;
        if (gr >= M) continue;
        #pragma unroll
        for (int j = 0; j < TN; j += 4) {
            int gc = bcol + tcol * TN + j;
            float4 v;
            v.x = acc[i][j + 0] + bias[gc + 0];
            v.y = acc[i][j + 1] + bias[gc + 1];
            v.z = acc[i][j + 2] + bias[gc + 2];
            v.w = acc[i][j + 3] + bias[gc + 3];
            if (LEAKY) {
                v.x = (v.x > 0.f) ? v.x : SLOPE * v.x;
                v.y = (v.y > 0.f) ? v.y : SLOPE * v.y;
                v.z = (v.z > 0.f) ? v.z : SLOPE * v.z;
                v.w = (v.w > 0.f) ? v.w : SLOPE * v.w;
            }
            *(float4*)(C + (size_t)gr * ldc + gc) = v;
        }
    }
}

// ---------------- launcher ----------------
extern "C" void kernel_launch(void* const* d_in, const int* in_sizes, int n_in,
                              void* d_out, int out_size) {
    const float* x      = (const float*)d_in[0];
    const void*  ei     = d_in[1];
    const float* ea     = (const float*)d_in[2];
    const float* in_W   = (const float*)d_in[3];
    const float* in_b   = (const float*)d_in[4];
    const float* eW     = (const float*)d_in[5];
    const float* eB     = (const float*)d_in[6];
    const float* W1     = (const float*)d_in[7];
    const float* b1     = (const float*)d_in[8];
    const float* ln_g   = (const float*)d_in[9];
    const float* ln_b   = (const float*)d_in[10];
    const float* W2     = (const float*)d_in[11];
    const float* b2     = (const float*)d_in[12];
    const float* W3     = (const float*)d_in[13];
    const float* b3     = (const float*)d_in[14];
    const float* out_W  = (const float*)d_in[15];
    const float* out_b  = (const float*)d_in[16];
    float* out = (float*)d_out;

    float* HID; cudaGetSymbolAddress((void**)&HID, g_HID);
    float* Z;   cudaGetSymbolAddress((void**)&Z,   g_Z);
    float* T1;  cudaGetSymbolAddress((void**)&T1,  g_T1);
    float* T2;  cudaGetSymbolAddress((void**)&T2,  g_T2);

    // 0) int32/int64 edge-index detection
    detect_kernel<<<1, 1024>>>((const unsigned int*)ei);

    // 1) h0 = x @ in_W + in_b  -> HID[:, 0:128]
    sgemm_kernel<64, 128, 16, 4, 8, false><<<dim3(157, 1), 256>>>(
        NN, 128, 128, x, D_IN, in_W, HH, in_b, HID, 512);

    // 2) GINE layers
    for (int l = 0; l < LL; l++) {
        int hid_off = l * HH;             // current h lives at HID[:, l*128 : (l+1)*128]
        const float* eWl = eW + l * D_CAT;
        const float* eBl = eB + l * D_CAT;
        const float* W1l = W1 + (size_t)l * D_CAT * WH;
        const float* b1l = b1 + l * WH;
        const float* gl  = ln_g + l * WH;
        const float* bbl = ln_b + l * WH;
        const float* W2l = W2 + (size_t)l * WH * WH;
        const float* b2l = b2 + l * WH;
        const float* W3l = W3 + (size_t)l * WH * HH;
        const float* b3l = b3 + l * HH;

        // Z = xc
        init_z_kernel<<<(NN * 64 + 255) / 256, 256>>>(x, hid_off);
        // Z += segment_sum(relu(xc[src] + ea*eW + eB), dst)
        edge_kernel<<<EE / 4, 256>>>(ei, ea, eWl, eBl, x, hid_off);
        // T1 = Z @ W1 + b1
        sgemm_kernel<128, 128, 16, 8, 8, false><<<dim3(79, 2), 256>>>(
            NN, WH, D_CAT, Z, D_CAT, W1l, WH, b1l, T1, WH);
        // T1 = leaky(LN(T1)*g + b)
        ln_leaky_kernel<<<NN, 256>>>(T1, gl, bbl);
        // T2 = leaky(T1 @ W2 + b2)
        sgemm_kernel<128, 128, 16, 8, 8, true><<<dim3(79, 2), 256>>>(
            NN, WH, WH, T1, WH, W2l, WH, b2l, T2, WH);
        // h_{l+1} = T2 @ W3 + b3 -> HID[:, (l+1)*128 : (l+2)*128]
        sgemm_kernel<64, 128, 16, 4, 8, false><<<dim3(157, 1), 256>>>(
            NN, HH, WH, T2, WH, W3l, HH, b3l, HID + (l + 1) * HH, 512);
    }

    // 3) out = HID @ out_W + out_b
    sgemm_kernel<64, 128, 16, 4, 8, false><<<dim3(157, 1), 256>>>(
        NN, D_OUT, 512, HID, 512, out_W, D_OUT, out_b, out, D_OUT);

    (void)in_sizes; (void)n_in; (void)out_size;
}

// round 2
// speedup vs baseline: 1.4046x; 1.4046x over previous
#include <cuda_runtime.h>
#include <cuda_bf16.h>
#include <cstdint>

// ---------------- problem constants ----------------
#define NN      10000
#define EE      320000
#define D_IN    128
#define HH      128
#define LL      3
#define D_CAT   256      // D_IN + H
#define WH      256      // 2*H
#define D_OUT   128
#define LN_EPS  1e-5f
#define SLOPE   0.1f

// ---------------- scratch (no allocation allowed) ----------------
__device__ float g_HID[NN * 512];   // [h0 | h1 | h2 | h3]
__device__ float g_Z  [NN * D_CAT]; // xc + agg
__device__ float g_T1 [NN * WH];
__device__ float g_T2 [NN * WH];
__device__ int   g_is_i64;

// ---------------- edge-index dtype detection ----------------
// If the buffer holds int64 little-endian indices in [0,10000), every odd
// 32-bit word is 0. If it holds random int32 indices, that is (practically)
// never true for 1024 consecutive slots.
__global__ void detect_kernel(const unsigned int* __restrict__ w) {
    __shared__ int bad;
    if (threadIdx.x == 0) bad = 0;
    __syncthreads();
    unsigned int v = w[2 * threadIdx.x + 1];
    if (v != 0u) atomicExch(&bad, 1);
    __syncthreads();
    if (threadIdx.x == 0) g_is_i64 = (bad == 0) ? 1 : 0;
}

// ---------------- Z init: Z[n] = concat(x[n], h_l[n]) ----------------
__global__ void init_z_kernel(const float* __restrict__ x, int hid_off) {
    int i = blockIdx.x * blockDim.x + threadIdx.x;     // float4 index, N*64 total
    if (i >= NN * 64) return;
    int n  = i >> 6;
    int d4 = (i & 63) * 4;
    float4 v;
    if (d4 < 128) v = *(const float4*)(x + (size_t)n * D_IN + d4);
    else          v = *(const float4*)(g_HID + (size_t)n * 512 + hid_off + (d4 - 128));
    *(float4*)(g_Z + (size_t)n * D_CAT + d4) = v;
}

// ---------------- edge kernel: Z[dst] += relu(xc[src] + ea*eW + eB) ----------------
// 64 threads per edge, 4 floats per thread, ONE red.global.add.v4.f32 per thread.
__global__ void edge_kernel(const void* __restrict__ ei,
                            const float* __restrict__ ea,
                            const float* __restrict__ eWl,
                            const float* __restrict__ eBl,
                            const float* __restrict__ x,
                            int hid_off) {
    int e = blockIdx.x * 4 + (threadIdx.x >> 6);
    if (e >= EE) return;
    int lane = threadIdx.x & 63;
    int d = lane * 4;

    long long src, dst;
    if (g_is_i64) {
        src = ((const long long*)ei)[e];
        dst = ((const long long*)ei)[EE + e];
    } else {
        src = ((const int*)ei)[e];
        dst = ((const int*)ei)[EE + e];
    }
    float a = __ldg(ea + e);

    float4 xv;
    if (d < 128) xv = *(const float4*)(x + (size_t)src * D_IN + d);
    else         xv = *(const float4*)(g_HID + (size_t)src * 512 + hid_off + (d - 128));

    float4 w  = *(const float4*)(eWl + d);
    float4 bb = *(const float4*)(eBl + d);

    float m0 = fmaxf(xv.x + fmaf(a, w.x, bb.x), 0.0f);
    float m1 = fmaxf(xv.y + fmaf(a, w.y, bb.y), 0.0f);
    float m2 = fmaxf(xv.z + fmaf(a, w.z, bb.z), 0.0f);
    float m3 = fmaxf(xv.w + fmaf(a, w.w, bb.w), 0.0f);

    float* zp = g_Z + (size_t)dst * D_CAT + d;   // 16B-aligned (row base 1KB-aligned, d%4==0)
    asm volatile("red.global.add.v4.f32 [%0], {%1, %2, %3, %4};"
                 :: "l"(zp), "f"(m0), "f"(m1), "f"(m2), "f"(m3)
                 : "memory");
}

// ---------------- LayerNorm + LeakyReLU (row of 256) ----------------
__global__ void ln_leaky_kernel(float* __restrict__ T,
                                const float* __restrict__ g,
                                const float* __restrict__ b) {
    int row = blockIdx.x;
    int tid = threadIdx.x;                      // 256 threads
    float v = T[(size_t)row * WH + tid];

    float s = v, s2 = v * v;
    #pragma unroll
    for (int off = 16; off > 0; off >>= 1) {
        s  += __shfl_down_sync(0xffffffffu, s,  off);
        s2 += __shfl_down_sync(0xffffffffu, s2, off);
    }
    __shared__ float sh_s[8], sh_s2[8];
    int wid = tid >> 5, lid = tid & 31;
    if (lid == 0) { sh_s[wid] = s; sh_s2[wid] = s2; }
    __syncthreads();
    __shared__ float sh_mu, sh_rstd;
    if (tid == 0) {
        float ts = 0.f, ts2 = 0.f;
        #pragma unroll
        for (int i = 0; i < 8; i++) { ts += sh_s[i]; ts2 += sh_s2[i]; }
        float mu  = ts * (1.0f / WH);
        float var = ts2 * (1.0f / WH) - mu * mu;
        sh_mu = mu;
        sh_rstd = rsqrtf(var + LN_EPS);
    }
    __syncthreads();
    float y = (v - sh_mu) * sh_rstd * g[tid] + b[tid];
    T[(size_t)row * WH + tid] = (y > 0.f) ? y : SLOPE * y;
}

// ---------------- fp32 tiled GEMM:  C = A @ B + bias [, leaky] ----------------
// A: [M,K] row-major (lda), B: [K,N] row-major (ldb), C row-major (ldc).
// N must be a multiple of BN, K a multiple of BK. M is guarded.
template <int BM, int BN, int BK, int TM, int TN, bool LEAKY>
__global__ void sgemm_kernel(int M, int N, int K,
                             const float* __restrict__ A, int lda,
                             const float* __restrict__ B, int ldb,
                             const float* __restrict__ bias,
                             float* __restrict__ C, int ldc) {
    constexpr int THREADS = (BM / TM) * (BN / TN);   // 256
    __shared__ float As[BK][BM + 4];
    __shared__ float Bs[BK][BN + 4];

    const int tid  = threadIdx.x;
    const int tcol = tid % (BN / TN);
    const int trow = tid / (BN / TN);
    const int brow = blockIdx.x * BM;
    const int bcol = blockIdx.y * BN;

    float acc[TM][TN];
    #pragma unroll
    for (int i = 0; i < TM; i++)
        #pragma unroll
        for (int j = 0; j < TN; j++) acc[i][j] = 0.f;

    constexpr int A_LOADS = BM * BK / 4 / THREADS;
    constexpr int B_LOADS = BK * BN / 4 / THREADS;

    for (int k0 = 0; k0 < K; k0 += BK) {
        #pragma unroll
        for (int i = 0; i < A_LOADS; i++) {
            int idx = tid + i * THREADS;
            int r   = idx / (BK / 4);
            int c4  = (idx % (BK / 4)) * 4;
            int gr  = brow + r;
            float4 v = make_float4(0.f, 0.f, 0.f, 0.f);
            if (gr < M) v = *(const float4*)(A + (size_t)gr * lda + k0 + c4);
            As[c4 + 0][r] = v.x;
            As[c4 + 1][r] = v.y;
            As[c4 + 2][r] = v.z;
            As[c4 + 3][r] = v.w;
        }
        #pragma unroll
        for (int i = 0; i < B_LOADS; i++) {
            int idx = tid + i * THREADS;
            int r   = idx / (BN / 4);
            int c4  = (idx % (BN / 4)) * 4;
            *(float4*)&Bs[r][c4] = *(const float4*)(B + (size_t)(k0 + r) * ldb + bcol + c4);
        }
        __syncthreads();

        #pragma unroll
        for (int kk = 0; kk < BK; kk++) {
            float a[TM], bv[TN];
            #pragma unroll
            for (int i = 0; i < TM; i += 4)
                *(float4*)&a[i] = *(const float4*)&As[kk][trow * TM + i];
            #pragma unroll
            for (int j = 0; j < TN; j += 4)
                *(float4*)&bv[j] = *(const float4*)&Bs[kk][tcol * TN + j];
            #pragma unroll
            for (int i = 0; i < TM; i++)
                #pragma unroll
                for (int j = 0; j < TN; j++)
                    acc[i][j] = fmaf(a[i], bv[j], acc[i][j]);
        }
        __syncthreads();
    }

    #pragma unroll
    for (int i = 0; i < TM; i++) {
        int gr = brow + trow * TM + i;
        if (gr >= M) continue;
        #pragma unroll
        for (int j = 0; j < TN; j += 4) {
            int gc = bcol + tcol * TN + j;
            float4 v;
            v.x = acc[i][j + 0] + bias[gc + 0];
            v.y = acc[i][j + 1] + bias[gc + 1];
            v.z = acc[i][j + 2] + bias[gc + 2];
            v.w = acc[i][j + 3] + bias[gc + 3];
            if (LEAKY) {
                v.x = (v.x > 0.f) ? v.x : SLOPE * v.x;
                v.y = (v.y > 0.f) ? v.y : SLOPE * v.y;
                v.z = (v.z > 0.f) ? v.z : SLOPE * v.z;
                v.w = (v.w > 0.f) ? v.w : SLOPE * v.w;
            }
            *(float4*)(C + (size_t)gr * ldc + gc) = v;
        }
    }
}

// ---------------- launcher ----------------
extern "C" void kernel_launch(void* const* d_in, const int* in_sizes, int n_in,
                              void* d_out, int out_size) {
    const float* x      = (const float*)d_in[0];
    const void*  ei     = d_in[1];
    const float* ea     = (const float*)d_in[2];
    const float* in_W   = (const float*)d_in[3];
    const float* in_b   = (const float*)d_in[4];
    const float* eW     = (const float*)d_in[5];
    const float* eB     = (const float*)d_in[6];
    const float* W1     = (const float*)d_in[7];
    const float* b1     = (const float*)d_in[8];
    const float* ln_g   = (const float*)d_in[9];
    const float* ln_b   = (const float*)d_in[10];
    const float* W2     = (const float*)d_in[11];
    const float* b2     = (const float*)d_in[12];
    const float* W3     = (const float*)d_in[13];
    const float* b3     = (const float*)d_in[14];
    const float* out_W  = (const float*)d_in[15];
    const float* out_b  = (const float*)d_in[16];
    float* out = (float*)d_out;

    float* HID; cudaGetSymbolAddress((void**)&HID, g_HID);
    float* Z;   cudaGetSymbolAddress((void**)&Z,   g_Z);
    float* T1;  cudaGetSymbolAddress((void**)&T1,  g_T1);
    float* T2;  cudaGetSymbolAddress((void**)&T2,  g_T2);

    // 0) int32/int64 edge-index detection
    detect_kernel<<<1, 1024>>>((const unsigned int*)ei);

    // 1) h0 = x @ in_W + in_b  -> HID[:, 0:128]
    sgemm_kernel<64, 128, 16, 4, 8, false><<<dim3(157, 1), 256>>>(
        NN, 128, 128, x, D_IN, in_W, HH, in_b, HID, 512);

    // 2) GINE layers
    for (int l = 0; l < LL; l++) {
        int hid_off = l * HH;             // current h lives at HID[:, l*128 : (l+1)*128]
        const float* eWl = eW + l * D_CAT;
        const float* eBl = eB + l * D_CAT;
        const float* W1l = W1 + (size_t)l * D_CAT * WH;
        const float* b1l = b1 + l * WH;
        const float* gl  = ln_g + l * WH;
        const float* bbl = ln_b + l * WH;
        const float* W2l = W2 + (size_t)l * WH * WH;
        const float* b2l = b2 + l * WH;
        const float* W3l = W3 + (size_t)l * WH * HH;
        const float* b3l = b3 + l * HH;

        // Z = xc
        init_z_kernel<<<(NN * 64 + 255) / 256, 256>>>(x, hid_off);
        // Z += segment_sum(relu(xc[src] + ea*eW + eB), dst)
        edge_kernel<<<EE / 4, 256>>>(ei, ea, eWl, eBl, x, hid_off);
        // T1 = Z @ W1 + b1
        sgemm_kernel<128, 128, 16, 8, 8, false><<<dim3(79, 2), 256>>>(
            NN, WH, D_CAT, Z, D_CAT, W1l, WH, b1l, T1, WH);
        // T1 = leaky(LN(T1)*g + b)
        ln_leaky_kernel<<<NN, 256>>>(T1, gl, bbl);
        // T2 = leaky(T1 @ W2 + b2)
        sgemm_kernel<128, 128, 16, 8, 8, true><<<dim3(79, 2), 256>>>(
            NN, WH, WH, T1, WH, W2l, WH, b2l, T2, WH);
        // h_{l+1} = T2 @ W3 + b3 -> HID[:, (l+1)*128 : (l+2)*128]
        sgemm_kernel<64, 128, 16, 4, 8, false><<<dim3(157, 1), 256>>>(
            NN, HH, WH, T2, WH, W3l, HH, b3l, HID + (l + 1) * HH, 512);
    }

    // 3) out = HID @ out_W + out_b
    sgemm_kernel<64, 128, 16, 4, 8, false><<<dim3(157, 1), 256>>>(
        NN, D_OUT, 512, HID, 512, out_W, D_OUT, out_b, out, D_OUT);

    (void)in_sizes; (void)n_in; (void)out_size;
}

// round 3
// speedup vs baseline: 1.5123x; 1.0767x over previous
#include <cuda_runtime.h>
#include <cuda_bf16.h>
#include <cstdint>

// ---------------- problem constants ----------------
#define NN      10000
#define EE      320000
#define D_IN    128
#define HH      128
#define LL      3
#define D_CAT   256      // D_IN + H
#define WH      256      // 2*H
#define D_OUT   128
#define LN_EPS  1e-5f
#define SLOPE   0.1f

// ---------------- scratch (no allocation allowed) ----------------
__device__ float g_HID[NN * 512];   // [h0 | h1 | h2 | h3]
__device__ float g_Z  [NN * D_CAT]; // xc + agg
__device__ float g_T1 [NN * WH];
__device__ float g_T2 [NN * WH];
__device__ int   g_is_i64;

// ---------------- edge-index dtype detection ----------------
__global__ void detect_kernel(const unsigned int* __restrict__ w) {
    __shared__ int bad;
    if (threadIdx.x == 0) bad = 0;
    __syncthreads();
    unsigned int v = w[2 * threadIdx.x + 1];
    if (v != 0u) atomicExch(&bad, 1);
    __syncthreads();
    if (threadIdx.x == 0) g_is_i64 = (bad == 0) ? 1 : 0;
}

// ---------------- Z init: Z[n] = concat(x[n], h_l[n]) ----------------
__global__ void init_z_kernel(const float* __restrict__ x, int hid_off) {
    int i = blockIdx.x * blockDim.x + threadIdx.x;     // float4 index, N*64 total
    if (i >= NN * 64) return;
    int n  = i >> 6;
    int d4 = (i & 63) * 4;
    float4 v;
    if (d4 < 128) v = *(const float4*)(x + (size_t)n * D_IN + d4);
    else          v = *(const float4*)(g_HID + (size_t)n * 512 + hid_off + (d4 - 128));
    *(float4*)(g_Z + (size_t)n * D_CAT + d4) = v;
}

// ---------------- edge kernel: Z[dst] += relu(xc[src] + ea*eW + eB) ----------------
__global__ void edge_kernel(const void* __restrict__ ei,
                            const float* __restrict__ ea,
                            const float* __restrict__ eWl,
                            const float* __restrict__ eBl,
                            const float* __restrict__ x,
                            int hid_off) {
    int e = blockIdx.x * 4 + (threadIdx.x >> 6);
    if (e >= EE) return;
    int lane = threadIdx.x & 63;
    int d = lane * 4;

    long long src, dst;
    if (g_is_i64) {
        src = ((const long long*)ei)[e];
        dst = ((const long long*)ei)[EE + e];
    } else {
        src = ((const int*)ei)[e];
        dst = ((const int*)ei)[EE + e];
    }
    float a = __ldg(ea + e);

    float4 xv;
    if (d < 128) xv = *(const float4*)(x + (size_t)src * D_IN + d);
    else         xv = *(const float4*)(g_HID + (size_t)src * 512 + hid_off + (d - 128));

    float4 w  = *(const float4*)(eWl + d);
    float4 bb = *(const float4*)(eBl + d);

    float m0 = fmaxf(xv.x + fmaf(a, w.x, bb.x), 0.0f);
    float m1 = fmaxf(xv.y + fmaf(a, w.y, bb.y), 0.0f);
    float m2 = fmaxf(xv.z + fmaf(a, w.z, bb.z), 0.0f);
    float m3 = fmaxf(xv.w + fmaf(a, w.w, bb.w), 0.0f);

    float* zp = g_Z + (size_t)dst * D_CAT + d;   // 16B-aligned
    asm volatile("red.global.add.v4.f32 [%0], {%1, %2, %3, %4};"
                 :: "l"(zp), "f"(m0), "f"(m1), "f"(m2), "f"(m3)
                 : "memory");
}

// ---------------- LayerNorm + LeakyReLU (row of 256) ----------------
__global__ void ln_leaky_kernel(float* __restrict__ T,
                                const float* __restrict__ g,
                                const float* __restrict__ b) {
    int row = blockIdx.x;
    int tid = threadIdx.x;                      // 256 threads
    float v = T[(size_t)row * WH + tid];

    float s = v, s2 = v * v;
    #pragma unroll
    for (int off = 16; off > 0; off >>= 1) {
        s  += __shfl_down_sync(0xffffffffu, s,  off);
        s2 += __shfl_down_sync(0xffffffffu, s2, off);
    }
    __shared__ float sh_s[8], sh_s2[8];
    int wid = tid >> 5, lid = tid & 31;
    if (lid == 0) { sh_s[wid] = s; sh_s2[wid] = s2; }
    __syncthreads();
    __shared__ float sh_mu, sh_rstd;
    if (tid == 0) {
        float ts = 0.f, ts2 = 0.f;
        #pragma unroll
        for (int i = 0; i < 8; i++) { ts += sh_s[i]; ts2 += sh_s2[i]; }
        float mu  = ts * (1.0f / WH);
        float var = ts2 * (1.0f / WH) - mu * mu;
        sh_mu = mu;
        sh_rstd = rsqrtf(var + LN_EPS);
    }
    __syncthreads();
    float y = (v - sh_mu) * sh_rstd * g[tid] + b[tid];
    T[(size_t)row * WH + tid] = (y > 0.f) ? y : SLOPE * y;
}

// ---------------- tf32x3 tensor-core GEMM ----------------
// C = A @ B + bias [, leaky].  A:[M,K] rm, B:[K,N] rm, C rm.
// CTA tile 128x128, BK=16, 8 warps (warp tile 64x32), mma.m16n8k8.tf32,
// 3-term split: AhiBhi + AhiBlo + AloBhi  ->  ~fp32 accuracy.
__device__ __forceinline__ unsigned f2tf32(float v) {
    unsigned r;
    asm("cvt.rna.tf32.f32 %0, %1;" : "=r"(r) : "f"(v));
    return r;
}
__device__ __forceinline__ void mma_tf32(float* c, const unsigned* a, const unsigned* b) {
    asm volatile(
        "mma.sync.aligned.m16n8k8.row.col.f32.tf32.tf32.f32 "
        "{%0,%1,%2,%3}, {%4,%5,%6,%7}, {%8,%9}, {%0,%1,%2,%3};"
        : "+f"(c[0]), "+f"(c[1]), "+f"(c[2]), "+f"(c[3])
        : "r"(a[0]), "r"(a[1]), "r"(a[2]), "r"(a[3]), "r"(b[0]), "r"(b[1]));
}

template <bool LEAKY>
__global__ __launch_bounds__(256, 1)
void tf32_gemm_kernel(int M, int N, int K,
                      const float* __restrict__ A, int lda,
                      const float* __restrict__ B, int ldb,
                      const float* __restrict__ bias,
                      float* __restrict__ C, int ldc) {
    // A [row][k], stride 20: bank = 4*row + k (mod 32) -> conflict-free frag loads
    __shared__ float Ah[128][20], Al[128][20];
    // B [k][n], stride 136: bank = 8*k + n (mod 32) -> conflict-free
    __shared__ float Bh[16][136], Bl[16][136];

    const int tid   = threadIdx.x;
    const int w     = tid >> 5;
    const int lane  = tid & 31;
    const int g     = lane >> 2;     // 0..7
    const int q     = lane & 3;      // 0..3
    const int warpM = (w >> 2) * 64; // 0 or 64
    const int warpN = (w & 3) * 32;  // 0,32,64,96
    const int brow  = blockIdx.x * 128;
    const int bcol  = blockIdx.y * 128;

    float acc[4][4][4];
    #pragma unroll
    for (int mt = 0; mt < 4; mt++)
        #pragma unroll
        for (int nt = 0; nt < 4; nt++)
            #pragma unroll
            for (int i = 0; i < 4; i++) acc[mt][nt][i] = 0.f;

    for (int k0 = 0; k0 < K; k0 += 16) {
        // stage A (split hi/lo): 128x16 floats = 512 float4 / 256 threads
        #pragma unroll
        for (int i = 0; i < 2; i++) {
            int idx = tid + i * 256;
            int r   = idx >> 2;
            int kq  = (idx & 3) * 4;
            float4 v = make_float4(0.f, 0.f, 0.f, 0.f);
            if (brow + r < M)
                v = *(const float4*)(A + (size_t)(brow + r) * lda + k0 + kq);
            float vv[4] = {v.x, v.y, v.z, v.w};
            #pragma unroll
            for (int j = 0; j < 4; j++) {
                unsigned hi = f2tf32(vv[j]);
                float lof   = vv[j] - __uint_as_float(hi);
                Ah[r][kq + j] = __uint_as_float(hi);
                Al[r][kq + j] = __uint_as_float(f2tf32(lof));
            }
        }
        // stage B (split hi/lo): 16x128 floats = 512 float4 / 256 threads
        #pragma unroll
        for (int i = 0; i < 2; i++) {
            int idx = tid + i * 256;
            int r   = idx >> 5;
            int n4  = (idx & 31) * 4;
            float4 v = *(const float4*)(B + (size_t)(k0 + r) * ldb + bcol + n4);
            float vv[4] = {v.x, v.y, v.z, v.w};
            #pragma unroll
            for (int j = 0; j < 4; j++) {
                unsigned hi = f2tf32(vv[j]);
                float lof   = vv[j] - __uint_as_float(hi);
                Bh[r][n4 + j] = __uint_as_float(hi);
                Bl[r][n4 + j] = __uint_as_float(f2tf32(lof));
            }
        }
        __syncthreads();

        #pragma unroll
        for (int ks = 0; ks < 2; ks++) {
            const int kb = ks * 8;
            unsigned ah[4][4], al[4][4], bh[4][2], bl[4][2];
            #pragma unroll
            for (int mt = 0; mt < 4; mt++) {
                int r0 = warpM + mt * 16 + g;
                ah[mt][0] = __float_as_uint(Ah[r0    ][kb + q    ]);
                ah[mt][1] = __float_as_uint(Ah[r0 + 8][kb + q    ]);
                ah[mt][2] = __float_as_uint(Ah[r0    ][kb + q + 4]);
                ah[mt][3] = __float_as_uint(Ah[r0 + 8][kb + q + 4]);
                al[mt][0] = __float_as_uint(Al[r0    ][kb + q    ]);
                al[mt][1] = __float_as_uint(Al[r0 + 8][kb + q    ]);
                al[mt][2] = __float_as_uint(Al[r0    ][kb + q + 4]);
                al[mt][3] = __float_as_uint(Al[r0 + 8][kb + q + 4]);
            }
            #pragma unroll
            for (int nt = 0; nt < 4; nt++) {
                int c0 = warpN + nt * 8 + g;
                bh[nt][0] = __float_as_uint(Bh[kb + q    ][c0]);
                bh[nt][1] = __float_as_uint(Bh[kb + q + 4][c0]);
                bl[nt][0] = __float_as_uint(Bl[kb + q    ][c0]);
                bl[nt][1] = __float_as_uint(Bl[kb + q + 4][c0]);
            }
            #pragma unroll
            for (int mt = 0; mt < 4; mt++)
                #pragma unroll
                for (int nt = 0; nt < 4; nt++) {
                    mma_tf32(acc[mt][nt], ah[mt], bh[nt]);
                    mma_tf32(acc[mt][nt], ah[mt], bl[nt]);
                    mma_tf32(acc[mt][nt], al[mt], bh[nt]);
                }
        }
        __syncthreads();
    }

    // epilogue: bias (+ optional leaky), guarded stores
    #pragma unroll
    for (int nt = 0; nt < 4; nt++) {
        int gc = bcol + warpN + nt * 8 + 2 * q;
        float bx = bias[gc], by = bias[gc + 1];
        #pragma unroll
        for (int mt = 0; mt < 4; mt++) {
            int gr0 = brow + warpM + mt * 16 + g;
            float v0 = acc[mt][nt][0] + bx;
            float v1 = acc[mt][nt][1] + by;
            float v2 = acc[mt][nt][2] + bx;
            float v3 = acc[mt][nt][3] + by;
            if (LEAKY) {
                v0 = (v0 > 0.f) ? v0 : SLOPE * v0;
                v1 = (v1 > 0.f) ? v1 : SLOPE * v1;
                v2 = (v2 > 0.f) ? v2 : SLOPE * v2;
                v3 = (v3 > 0.f) ? v3 : SLOPE * v3;
            }
            if (gr0 < M) {
                float2 p = make_float2(v0, v1);
                *(float2*)(C + (size_t)gr0 * ldc + gc) = p;
            }
            if (gr0 + 8 < M) {
                float2 p = make_float2(v2, v3);
                *(float2*)(C + (size_t)(gr0 + 8) * ldc + gc) = p;
            }
        }
    }
}

// ---------------- launcher ----------------
extern "C" void kernel_launch(void* const* d_in, const int* in_sizes, int n_in,
                              void* d_out, int out_size) {
    const float* x      = (const float*)d_in[0];
    const void*  ei     = d_in[1];
    const float* ea     = (const float*)d_in[2];
    const float* in_W   = (const float*)d_in[3];
    const float* in_b   = (const float*)d_in[4];
    const float* eW     = (const float*)d_in[5];
    const float* eB     = (const float*)d_in[6];
    const float* W1     = (const float*)d_in[7];
    const float* b1     = (const float*)d_in[8];
    const float* ln_g   = (const float*)d_in[9];
    const float* ln_b   = (const float*)d_in[10];
    const float* W2     = (const float*)d_in[11];
    const float* b2     = (const float*)d_in[12];
    const float* W3     = (const float*)d_in[13];
    const float* b3     = (const float*)d_in[14];
    const float* out_W  = (const float*)d_in[15];
    const float* out_b  = (const float*)d_in[16];
    float* out = (float*)d_out;

    float* HID; cudaGetSymbolAddress((void**)&HID, g_HID);
    float* Z;   cudaGetSymbolAddress((void**)&Z,   g_Z);
    float* T1;  cudaGetSymbolAddress((void**)&T1,  g_T1);
    float* T2;  cudaGetSymbolAddress((void**)&T2,  g_T2);

    // 0) int32/int64 edge-index detection
    detect_kernel<<<1, 1024>>>((const unsigned int*)ei);

    // 1) h0 = x @ in_W + in_b  -> HID[:, 0:128]
    tf32_gemm_kernel<false><<<dim3(79, 1), 256>>>(
        NN, 128, 128, x, D_IN, in_W, HH, in_b, HID, 512);

    // 2) GINE layers
    for (int l = 0; l < LL; l++) {
        int hid_off = l * HH;
        const float* eWl = eW + l * D_CAT;
        const float* eBl = eB + l * D_CAT;
        const float* W1l = W1 + (size_t)l * D_CAT * WH;
        const float* b1l = b1 + l * WH;
        const float* gl  = ln_g + l * WH;
        const float* bbl = ln_b + l * WH;
        const float* W2l = W2 + (size_t)l * WH * WH;
        const float* b2l = b2 + l * WH;
        const float* W3l = W3 + (size_t)l * WH * HH;
        const float* b3l = b3 + l * HH;

        // Z = xc
        init_z_kernel<<<(NN * 64 + 255) / 256, 256>>>(x, hid_off);
        // Z += segment_sum(relu(xc[src] + ea*eW + eB), dst)
        edge_kernel<<<EE / 4, 256>>>(ei, ea, eWl, eBl, x, hid_off);
        // T1 = Z @ W1 + b1
        tf32_gemm_kernel<false><<<dim3(79, 2), 256>>>(
            NN, WH, D_CAT, Z, D_CAT, W1l, WH, b1l, T1, WH);
        // T1 = leaky(LN(T1)*g + b)
        ln_leaky_kernel<<<NN, 256>>>(T1, gl, bbl);
        // T2 = leaky(T1 @ W2 + b2)
        tf32_gemm_kernel<true><<<dim3(79, 2), 256>>>(
            NN, WH, WH, T1, WH, W2l, WH, b2l, T2, WH);
        // h_{l+1} = T2 @ W3 + b3 -> HID[:, (l+1)*128 : (l+2)*128]
        tf32_gemm_kernel<false><<<dim3(79, 1), 256>>>(
            NN, HH, WH, T2, WH, W3l, HH, b3l, HID + (l + 1) * HH, 512);
    }

    // 3) out = HID @ out_W + out_b
    tf32_gemm_kernel<false><<<dim3(79, 1), 256>>>(
        NN, D_OUT, 512, HID, 512, out_W, D_OUT, out_b, out, D_OUT);

    (void)in_sizes; (void)n_in; (void)out_size;
}

// round 4
// speedup vs baseline: 2.5447x; 1.6827x over previous
#include <cuda_runtime.h>
#include <cuda_bf16.h>
#include <cstdint>

// ---------------- problem constants ----------------
#define NN      10000
#define EE      320000
#define D_IN    128
#define HH      128
#define LL      3
#define D_CAT   256      // D_IN + H
#define WH      256      // 2*H
#define D_OUT   128
#define LN_EPS  1e-5f
#define SLOPE   0.1f

// ---------------- scratch (no allocation allowed) ----------------
__device__ float g_HID[NN * 512];   // [h0 | h1 | h2 | h3]
__device__ float g_Z  [NN * D_CAT]; // xc + agg
__device__ float g_T1 [NN * WH];
__device__ float g_T2 [NN * WH];
__device__ int   g_is_i64;

// ---------------- edge-index dtype detection ----------------
__global__ void detect_kernel(const unsigned int* __restrict__ w) {
    __shared__ int bad;
    if (threadIdx.x == 0) bad = 0;
    __syncthreads();
    unsigned int v = w[2 * threadIdx.x + 1];
    if (v != 0u) atomicExch(&bad, 1);
    __syncthreads();
    if (threadIdx.x == 0) g_is_i64 = (bad == 0) ? 1 : 0;
}

// ---------------- Z init: Z[n] = concat(x[n], h_l[n]) ----------------
__global__ void init_z_kernel(const float* __restrict__ x, int hid_off) {
    int i = blockIdx.x * blockDim.x + threadIdx.x;     // float4 index, N*64 total
    if (i >= NN * 64) return;
    int n  = i >> 6;
    int d4 = (i & 63) * 4;
    float4 v;
    if (d4 < 128) v = *(const float4*)(x + (size_t)n * D_IN + d4);
    else          v = *(const float4*)(g_HID + (size_t)n * 512 + hid_off + (d4 - 128));
    *(float4*)(g_Z + (size_t)n * D_CAT + d4) = v;
}

// ---------------- edge kernel: Z[dst] += relu(xc[src] + ea*eW + eB) ----------------
__global__ void edge_kernel(const void* __restrict__ ei,
                            const float* __restrict__ ea,
                            const float* __restrict__ eWl,
                            const float* __restrict__ eBl,
                            const float* __restrict__ x,
                            int hid_off) {
    int e = blockIdx.x * 4 + (threadIdx.x >> 6);
    if (e >= EE) return;
    int lane = threadIdx.x & 63;
    int d = lane * 4;

    long long src, dst;
    if (g_is_i64) {
        src = ((const long long*)ei)[e];
        dst = ((const long long*)ei)[EE + e];
    } else {
        src = ((const int*)ei)[e];
        dst = ((const int*)ei)[EE + e];
    }
    float a = __ldg(ea + e);

    float4 xv;
    if (d < 128) xv = *(const float4*)(x + (size_t)src * D_IN + d);
    else         xv = *(const float4*)(g_HID + (size_t)src * 512 + hid_off + (d - 128));

    float4 w  = *(const float4*)(eWl + d);
    float4 bb = *(const float4*)(eBl + d);

    float m0 = fmaxf(xv.x + fmaf(a, w.x, bb.x), 0.0f);
    float m1 = fmaxf(xv.y + fmaf(a, w.y, bb.y), 0.0f);
    float m2 = fmaxf(xv.z + fmaf(a, w.z, bb.z), 0.0f);
    float m3 = fmaxf(xv.w + fmaf(a, w.w, bb.w), 0.0f);

    float* zp = g_Z + (size_t)dst * D_CAT + d;   // 16B-aligned
    asm volatile("red.global.add.v4.f32 [%0], {%1, %2, %3, %4};"
                 :: "l"(zp), "f"(m0), "f"(m1), "f"(m2), "f"(m3)
                 : "memory");
}

// ---------------- LayerNorm + LeakyReLU (row of 256) ----------------
__global__ void ln_leaky_kernel(float* __restrict__ T,
                                const float* __restrict__ g,
                                const float* __restrict__ b) {
    int row = blockIdx.x;
    int tid = threadIdx.x;                      // 256 threads
    float v = T[(size_t)row * WH + tid];

    float s = v, s2 = v * v;
    #pragma unroll
    for (int off = 16; off > 0; off >>= 1) {
        s  += __shfl_down_sync(0xffffffffu, s,  off);
        s2 += __shfl_down_sync(0xffffffffu, s2, off);
    }
    __shared__ float sh_s[8], sh_s2[8];
    int wid = tid >> 5, lid = tid & 31;
    if (lid == 0) { sh_s[wid] = s; sh_s2[wid] = s2; }
    __syncthreads();
    __shared__ float sh_mu, sh_rstd;
    if (tid == 0) {
        float ts = 0.f, ts2 = 0.f;
        #pragma unroll
        for (int i = 0; i < 8; i++) { ts += sh_s[i]; ts2 += sh_s2[i]; }
        float mu  = ts * (1.0f / WH);
        float var = ts2 * (1.0f / WH) - mu * mu;
        sh_mu = mu;
        sh_rstd = rsqrtf(var + LN_EPS);
    }
    __syncthreads();
    float y = (v - sh_mu) * sh_rstd * g[tid] + b[tid];
    T[(size_t)row * WH + tid] = (y > 0.f) ? y : SLOPE * y;
}

// ================= bf16x3 tensor-core GEMM =================
// C = A @ B + bias [, leaky].  A:[M,K] rm, B:[K,N] rm, C rm.
// fp32 split into hi/lo bf16; D = AhiBhi + AhiBlo + AloBhi (err ~2^-16).
// CTA tile 128 x BN, k-step 16, 8 warps, mma.m16n8k16 + ldmatrix.

__device__ __forceinline__ void ldsm4(unsigned* r, const __nv_bfloat16* p) {
    unsigned a = (unsigned)__cvta_generic_to_shared(p);
    asm volatile("ldmatrix.sync.aligned.m8n8.x4.shared.b16 {%0,%1,%2,%3}, [%4];"
                 : "=r"(r[0]), "=r"(r[1]), "=r"(r[2]), "=r"(r[3]) : "r"(a));
}
__device__ __forceinline__ void ldsm4t(unsigned* r, const __nv_bfloat16* p) {
    unsigned a = (unsigned)__cvta_generic_to_shared(p);
    asm volatile("ldmatrix.sync.aligned.m8n8.x4.trans.shared.b16 {%0,%1,%2,%3}, [%4];"
                 : "=r"(r[0]), "=r"(r[1]), "=r"(r[2]), "=r"(r[3]) : "r"(a));
}
__device__ __forceinline__ void mma_bf16(float* c, const unsigned* a, const unsigned* b) {
    asm volatile("mma.sync.aligned.m16n8k16.row.col.f32.bf16.bf16.f32 "
                 "{%0,%1,%2,%3}, {%4,%5,%6,%7}, {%8,%9}, {%0,%1,%2,%3};"
                 : "+f"(c[0]), "+f"(c[1]), "+f"(c[2]), "+f"(c[3])
                 : "r"(a[0]), "r"(a[1]), "r"(a[2]), "r"(a[3]), "r"(b[0]), "r"(b[1]));
}
// split v -> hi/lo bf16 (as ushort)
__device__ __forceinline__ void split_bf16(float v, unsigned short& h, unsigned short& l) {
    __nv_bfloat16 hb = __float2bfloat16_rn(v);
    float res = v - __bfloat162float(hb);
    h = __bfloat16_as_ushort(hb);
    l = __bfloat16_as_ushort(__float2bfloat16_rn(res));
}

template <int BN, bool LEAKY>
__global__ __launch_bounds__(256, 2)
void bf16x3_gemm_kernel(int M, int K,
                        const float* __restrict__ A, int lda,
                        const float* __restrict__ B, int ldb,
                        const float* __restrict__ bias,
                        float* __restrict__ C, int ldc) {
    constexpr int NB8     = BN / 8;       // 16B chunks per B row
    constexpr int WARPS_N = BN / 32;      // 4 (BN=128) or 2 (BN=64)
    constexpr int WARPS_M = 8 / WARPS_N;  // 2 or 4
    constexpr int MT      = (128 / WARPS_M) / 16;   // 4 or 2
    constexpr int B_ITERS = BN / 64;      // float4 staging iters for B
    constexpr int F4_ROW  = BN / 4;       // float4s per B row

    __shared__ __align__(16) __nv_bfloat16 Ah[128 * 16], Al[128 * 16];
    __shared__ __align__(16) __nv_bfloat16 Bh[16 * BN],  Bl[16 * BN];

    const int tid   = threadIdx.x;
    const int w     = tid >> 5;
    const int lane  = tid & 31;
    const int g     = lane >> 2;
    const int q     = lane & 3;
    const int warpN = (w % WARPS_N) * 32;
    const int warpM = (w / WARPS_N) * (MT * 16);
    const int brow  = blockIdx.x * 128;
    const int bcol  = blockIdx.y * BN;

    float acc[MT][4][4];
    #pragma unroll
    for (int mt = 0; mt < MT; mt++)
        #pragma unroll
        for (int nt = 0; nt < 4; nt++)
            #pragma unroll
            for (int i = 0; i < 4; i++) acc[mt][nt][i] = 0.f;

    float4 pa[2], pb[B_ITERS];

    // ---- stage helpers ----
    auto load_tile = [&](int k0) {
        #pragma unroll
        for (int i = 0; i < 2; i++) {
            int idx = tid + i * 256;
            int r   = idx >> 2;
            int kq  = (idx & 3) * 4;
            pa[i] = (brow + r < M)
                  ? *(const float4*)(A + (size_t)(brow + r) * lda + k0 + kq)
                  : make_float4(0.f, 0.f, 0.f, 0.f);
        }
        #pragma unroll
        for (int i = 0; i < B_ITERS; i++) {
            int idx = tid + i * 256;
            int k   = idx / F4_ROW;
            int n4  = (idx % F4_ROW) * 4;
            pb[i] = *(const float4*)(B + (size_t)(k0 + k) * ldb + bcol + n4);
        }
    };
    auto store_tile = [&]() {
        #pragma unroll
        for (int i = 0; i < 2; i++) {
            int idx = tid + i * 256;
            int r   = idx >> 2;
            int kq  = (idx & 3) * 4;
            float vv[4] = {pa[i].x, pa[i].y, pa[i].z, pa[i].w};
            unsigned short h[4], l[4];
            #pragma unroll
            for (int j = 0; j < 4; j++) split_bf16(vv[j], h[j], l[j]);
            int ci = (r * 2 + ((kq >> 3) ^ ((r >> 2) & 1))) * 8 + (kq & 4);
            uint2 hp = make_uint2((unsigned)h[0] | ((unsigned)h[1] << 16),
                                  (unsigned)h[2] | ((unsigned)h[3] << 16));
            uint2 lp = make_uint2((unsigned)l[0] | ((unsigned)l[1] << 16),
                                  (unsigned)l[2] | ((unsigned)l[3] << 16));
            *(uint2*)&Ah[ci] = hp;
            *(uint2*)&Al[ci] = lp;
        }
        #pragma unroll
        for (int i = 0; i < B_ITERS; i++) {
            int idx = tid + i * 256;
            int k   = idx / F4_ROW;
            int n4  = (idx % F4_ROW) * 4;
            float vv[4] = {pb[i].x, pb[i].y, pb[i].z, pb[i].w};
            unsigned short h[4], l[4];
            #pragma unroll
            for (int j = 0; j < 4; j++) split_bf16(vv[j], h[j], l[j]);
            int ci = (k * NB8 + ((n4 >> 3) ^ (k & 7))) * 8 + (n4 & 4);
            uint2 hp = make_uint2((unsigned)h[0] | ((unsigned)h[1] << 16),
                                  (unsigned)h[2] | ((unsigned)h[3] << 16));
            uint2 lp = make_uint2((unsigned)l[0] | ((unsigned)l[1] << 16),
                                  (unsigned)l[2] | ((unsigned)l[3] << 16));
            *(uint2*)&Bh[ci] = hp;
            *(uint2*)&Bl[ci] = lp;
        }
    };

    // ---- pipeline: prefetch tile k0+16 while mma'ing tile k0 ----
    load_tile(0);
    store_tile();
    __syncthreads();

    for (int k0 = 0; k0 < K; k0 += 16) {
        bool more = (k0 + 16) < K;
        if (more) load_tile(k0 + 16);

        // B fragments (all nt), hi+lo
        unsigned bhf[4][2], blf[4][2];
        #pragma unroll
        for (int j = 0; j < 2; j++) {
            int k  = lane & 15;
            int n8 = ((warpN + j * 16) >> 3) + (lane >> 4);
            int ch = k * NB8 + (n8 ^ (k & 7));
            unsigned r4[4];
            ldsm4t(r4, &Bh[ch * 8]);
            bhf[2 * j][0] = r4[0]; bhf[2 * j][1] = r4[1];
            bhf[2 * j + 1][0] = r4[2]; bhf[2 * j + 1][1] = r4[3];
            ldsm4t(r4, &Bl[ch * 8]);
            blf[2 * j][0] = r4[0]; blf[2 * j][1] = r4[1];
            blf[2 * j + 1][0] = r4[2]; blf[2 * j + 1][1] = r4[3];
        }
        // A fragments per mt, 3-term mma
        #pragma unroll
        for (int mt = 0; mt < MT; mt++) {
            int r  = warpM + mt * 16 + (lane & 15);
            int kh = lane >> 4;
            int ch = r * 2 + (kh ^ ((r >> 2) & 1));
            unsigned ah[4], al[4];
            ldsm4(ah, &Ah[ch * 8]);
            ldsm4(al, &Al[ch * 8]);
            #pragma unroll
            for (int nt = 0; nt < 4; nt++) {
                mma_bf16(acc[mt][nt], ah, bhf[nt]);
                mma_bf16(acc[mt][nt], ah, blf[nt]);
                mma_bf16(acc[mt][nt], al, bhf[nt]);
            }
        }
        __syncthreads();
        if (more) {
            store_tile();
            __syncthreads();
        }
    }

    // ---- epilogue ----
    #pragma unroll
    for (int nt = 0; nt < 4; nt++) {
        int gc = bcol + warpN + nt * 8 + 2 * q;
        float bx = bias[gc], by = bias[gc + 1];
        #pragma unroll
        for (int mt = 0; mt < MT; mt++) {
            int gr0 = brow + warpM + mt * 16 + g;
            float v0 = acc[mt][nt][0] + bx;
            float v1 = acc[mt][nt][1] + by;
            float v2 = acc[mt][nt][2] + bx;
            float v3 = acc[mt][nt][3] + by;
            if (LEAKY) {
                v0 = (v0 > 0.f) ? v0 : SLOPE * v0;
                v1 = (v1 > 0.f) ? v1 : SLOPE * v1;
                v2 = (v2 > 0.f) ? v2 : SLOPE * v2;
                v3 = (v3 > 0.f) ? v3 : SLOPE * v3;
            }
            if (gr0 < M)     *(float2*)(C + (size_t)gr0 * ldc + gc)       = make_float2(v0, v1);
            if (gr0 + 8 < M) *(float2*)(C + (size_t)(gr0 + 8) * ldc + gc) = make_float2(v2, v3);
        }
    }
}

// ---------------- launcher ----------------
extern "C" void kernel_launch(void* const* d_in, const int* in_sizes, int n_in,
                              void* d_out, int out_size) {
    const float* x      = (const float*)d_in[0];
    const void*  ei     = d_in[1];
    const float* ea     = (const float*)d_in[2];
    const float* in_W   = (const float*)d_in[3];
    const float* in_b   = (const float*)d_in[4];
    const float* eW     = (const float*)d_in[5];
    const float* eB     = (const float*)d_in[6];
    const float* W1     = (const float*)d_in[7];
    const float* b1     = (const float*)d_in[8];
    const float* ln_g   = (const float*)d_in[9];
    const float* ln_b   = (const float*)d_in[10];
    const float* W2     = (const float*)d_in[11];
    const float* b2     = (const float*)d_in[12];
    const float* W3     = (const float*)d_in[13];
    const float* b3     = (const float*)d_in[14];
    const float* out_W  = (const float*)d_in[15];
    const float* out_b  = (const float*)d_in[16];
    float* out = (float*)d_out;

    float* HID; cudaGetSymbolAddress((void**)&HID, g_HID);
    float* Z;   cudaGetSymbolAddress((void**)&Z,   g_Z);
    float* T1;  cudaGetSymbolAddress((void**)&T1,  g_T1);
    float* T2;  cudaGetSymbolAddress((void**)&T2,  g_T2);

    // 0) int32/int64 edge-index detection
    detect_kernel<<<1, 1024>>>((const unsigned int*)ei);

    // 1) h0 = x @ in_W + in_b  -> HID[:, 0:128]   (N=128 -> BN=64, grid 79x2)
    bf16x3_gemm_kernel<64, false><<<dim3(79, 2), 256>>>(
        NN, 128, x, D_IN, in_W, HH, in_b, HID, 512);

    // 2) GINE layers
    for (int l = 0; l < LL; l++) {
        int hid_off = l * HH;
        const float* eWl = eW + l * D_CAT;
        const float* eBl = eB + l * D_CAT;
        const float* W1l = W1 + (size_t)l * D_CAT * WH;
        const float* b1l = b1 + l * WH;
        const float* gl  = ln_g + l * WH;
        const float* bbl = ln_b + l * WH;
        const float* W2l = W2 + (size_t)l * WH * WH;
        const float* b2l = b2 + l * WH;
        const float* W3l = W3 + (size_t)l * WH * HH;
        const float* b3l = b3 + l * HH;

        init_z_kernel<<<(NN * 64 + 255) / 256, 256>>>(x, hid_off);
        edge_kernel<<<EE / 4, 256>>>(ei, ea, eWl, eBl, x, hid_off);
        // T1 = Z @ W1 + b1       (N=256 -> BN=128, grid 79x2)
        bf16x3_gemm_kernel<128, false><<<dim3(79, 2), 256>>>(
            NN, D_CAT, Z, D_CAT, W1l, WH, b1l, T1, WH);
        ln_leaky_kernel<<<NN, 256>>>(T1, gl, bbl);
        // T2 = leaky(T1 @ W2 + b2)
        bf16x3_gemm_kernel<128, true><<<dim3(79, 2), 256>>>(
            NN, WH, T1, WH, W2l, WH, b2l, T2, WH);
        // h_{l+1} = T2 @ W3 + b3 (N=128 -> BN=64, grid 79x2)
        bf16x3_gemm_kernel<64, false><<<dim3(79, 2), 256>>>(
            NN, WH, T2, WH, W3l, HH, b3l, HID + (l + 1) * HH, 512);
    }

    // 3) out = HID @ out_W + out_b   (N=128, K=512 -> BN=64, grid 79x2)
    bf16x3_gemm_kernel<64, false><<<dim3(79, 2), 256>>>(
        NN, 512, HID, 512, out_W, D_OUT, out_b, out, D_OUT);

    (void)in_sizes; (void)n_in; (void)out_size;
}

// round 5
// speedup vs baseline: 3.3372x; 1.3114x over previous
#include <cuda_runtime.h>
#include <cuda_bf16.h>
#include <cstdint>

// ---------------- problem constants ----------------
#define NN      10000
#define EE      320000
#define D_IN    128
#define HH      128
#define LL      3
#define D_CAT   256      // D_IN + H
#define WH      256      // 2*H
#define D_OUT   128
#define LN_EPS  1e-5f
#define SLOPE   0.1f

// ---------------- scratch (no allocation allowed) ----------------
__device__ float g_HID[NN * 512];   // [h0 | h1 | h2 | h3]
__device__ float g_Z  [NN * D_CAT]; // xc + agg
__device__ float g_T1 [NN * WH];
__device__ float g_T2 [NN * WH];
__device__ int   g_is_i64;
// CSR-by-dst edge structure (rebuilt every launch; edges static across layers)
__device__ int   g_count [NN];
__device__ int   g_cursor[NN];
__device__ int   g_startp[NN + 1];
__device__ int2  g_srcea [EE];      // (src, ea bits)

// ---------------- edge-index dtype detection ----------------
__global__ void detect_kernel(const unsigned int* __restrict__ w) {
    __shared__ int bad;
    if (threadIdx.x == 0) bad = 0;
    __syncthreads();
    unsigned int v = w[2 * threadIdx.x + 1];
    if (v != 0u) atomicExch(&bad, 1);
    __syncthreads();
    if (threadIdx.x == 0) g_is_i64 = (bad == 0) ? 1 : 0;
}

// ---------------- counting sort by dst ----------------
__global__ void zero_kernel() {
    int i = blockIdx.x * blockDim.x + threadIdx.x;
    if (i < NN) g_count[i] = 0;
}

__global__ void hist_kernel(const void* __restrict__ ei) {
    int e = blockIdx.x * blockDim.x + threadIdx.x;
    if (e >= EE) return;
    int dst = g_is_i64 ? (int)((const long long*)ei)[EE + e]
                       : ((const int*)ei)[EE + e];
    atomicAdd(&g_count[dst], 1);
}

// single-block exclusive scan over 10000 counts (1024 threads, 10 per thread)
__global__ void scan_kernel() {
    __shared__ int ssum[1024];
    int t = threadIdx.x;
    int base = t * 10;
    int s = 0;
    #pragma unroll
    for (int j = 0; j < 10; j++) {
        int idx = base + j;
        if (idx < NN) s += g_count[idx];
    }
    ssum[t] = s;
    __syncthreads();
    int orig = s;
    for (int off = 1; off < 1024; off <<= 1) {
        int v = (t >= off) ? ssum[t - off] : 0;
        __syncthreads();
        ssum[t] += v;
        __syncthreads();
    }
    int run = ssum[t] - orig;     // exclusive prefix of this chunk
    #pragma unroll
    for (int j = 0; j < 10; j++) {
        int idx = base + j;
        if (idx < NN) {
            g_startp[idx] = run;
            g_cursor[idx] = run;
            run += g_count[idx];
        }
    }
    if (t == 0) g_startp[NN] = EE;
}

__global__ void scatter_kernel(const void* __restrict__ ei,
                               const float* __restrict__ ea) {
    int e = blockIdx.x * blockDim.x + threadIdx.x;
    if (e >= EE) return;
    int src, dst;
    if (g_is_i64) {
        src = (int)((const long long*)ei)[e];
        dst = (int)((const long long*)ei)[EE + e];
    } else {
        src = ((const int*)ei)[e];
        dst = ((const int*)ei)[EE + e];
    }
    int pos = atomicAdd(&g_cursor[dst], 1);
    g_srcea[pos] = make_int2(src, __float_as_int(__ldg(ea + e)));
}

// ---------------- aggregation (atomic-free): Z[n] = xc[n] + sum relu(xc[src]+a*eW+eB) ----------------
// 64 threads per node (4 nodes per 256-thr block), 4 dims per thread.
__global__ void agg_z_kernel(const float* __restrict__ x,
                             const float* __restrict__ eWl,
                             const float* __restrict__ eBl,
                             int hid_off) {
    int node = blockIdx.x * 4 + (threadIdx.x >> 6);
    if (node >= NN) return;
    int lane = threadIdx.x & 63;
    int d = lane * 4;

    float4 w  = *(const float4*)(eWl + d);
    float4 bb = *(const float4*)(eBl + d);

    // acc = own xc
    float4 acc;
    if (d < 128) acc = *(const float4*)(x + (size_t)node * D_IN + d);
    else         acc = *(const float4*)(g_HID + (size_t)node * 512 + hid_off + (d - 128));

    const float* gbase = (d < 128) ? (x + d) : (g_HID + hid_off + (d - 128));
    const size_t gstr  = (d < 128) ? D_IN : 512;

    int i   = g_startp[node];
    int end = g_startp[node + 1];

    for (; i + 4 <= end; i += 4) {
        int2 se0 = g_srcea[i];
        int2 se1 = g_srcea[i + 1];
        int2 se2 = g_srcea[i + 2];
        int2 se3 = g_srcea[i + 3];
        float4 v0 = *(const float4*)(gbase + (size_t)se0.x * gstr);
        float4 v1 = *(const float4*)(gbase + (size_t)se1.x * gstr);
        float4 v2 = *(const float4*)(gbase + (size_t)se2.x * gstr);
        float4 v3 = *(const float4*)(gbase + (size_t)se3.x * gstr);
        float a0 = __int_as_float(se0.y), a1 = __int_as_float(se1.y);
        float a2 = __int_as_float(se2.y), a3 = __int_as_float(se3.y);
        acc.x += fmaxf(v0.x + fmaf(a0, w.x, bb.x), 0.f);
        acc.y += fmaxf(v0.y + fmaf(a0, w.y, bb.y), 0.f);
        acc.z += fmaxf(v0.z + fmaf(a0, w.z, bb.z), 0.f);
        acc.w += fmaxf(v0.w + fmaf(a0, w.w, bb.w), 0.f);
        acc.x += fmaxf(v1.x + fmaf(a1, w.x, bb.x), 0.f);
        acc.y += fmaxf(v1.y + fmaf(a1, w.y, bb.y), 0.f);
        acc.z += fmaxf(v1.z + fmaf(a1, w.z, bb.z), 0.f);
        acc.w += fmaxf(v1.w + fmaf(a1, w.w, bb.w), 0.f);
        acc.x += fmaxf(v2.x + fmaf(a2, w.x, bb.x), 0.f);
        acc.y += fmaxf(v2.y + fmaf(a2, w.y, bb.y), 0.f);
        acc.z += fmaxf(v2.z + fmaf(a2, w.z, bb.z), 0.f);
        acc.w += fmaxf(v2.w + fmaf(a2, w.w, bb.w), 0.f);
        acc.x += fmaxf(v3.x + fmaf(a3, w.x, bb.x), 0.f);
        acc.y += fmaxf(v3.y + fmaf(a3, w.y, bb.y), 0.f);
        acc.z += fmaxf(v3.z + fmaf(a3, w.z, bb.z), 0.f);
        acc.w += fmaxf(v3.w + fmaf(a3, w.w, bb.w), 0.f);
    }
    for (; i < end; i++) {
        int2 se = g_srcea[i];
        float4 v = *(const float4*)(gbase + (size_t)se.x * gstr);
        float a = __int_as_float(se.y);
        acc.x += fmaxf(v.x + fmaf(a, w.x, bb.x), 0.f);
        acc.y += fmaxf(v.y + fmaf(a, w.y, bb.y), 0.f);
        acc.z += fmaxf(v.z + fmaf(a, w.z, bb.z), 0.f);
        acc.w += fmaxf(v.w + fmaf(a, w.w, bb.w), 0.f);
    }

    *(float4*)(g_Z + (size_t)node * D_CAT + d) = acc;
}

// ---------------- LayerNorm + LeakyReLU (row of 256) ----------------
__global__ void ln_leaky_kernel(float* __restrict__ T,
                                const float* __restrict__ g,
                                const float* __restrict__ b) {
    int row = blockIdx.x;
    int tid = threadIdx.x;                      // 256 threads
    float v = T[(size_t)row * WH + tid];

    float s = v, s2 = v * v;
    #pragma unroll
    for (int off = 16; off > 0; off >>= 1) {
        s  += __shfl_down_sync(0xffffffffu, s,  off);
        s2 += __shfl_down_sync(0xffffffffu, s2, off);
    }
    __shared__ float sh_s[8], sh_s2[8];
    int wid = tid >> 5, lid = tid & 31;
    if (lid == 0) { sh_s[wid] = s; sh_s2[wid] = s2; }
    __syncthreads();
    __shared__ float sh_mu, sh_rstd;
    if (tid == 0) {
        float ts = 0.f, ts2 = 0.f;
        #pragma unroll
        for (int i = 0; i < 8; i++) { ts += sh_s[i]; ts2 += sh_s2[i]; }
        float mu  = ts * (1.0f / WH);
        float var = ts2 * (1.0f / WH) - mu * mu;
        sh_mu = mu;
        sh_rstd = rsqrtf(var + LN_EPS);
    }
    __syncthreads();
    float y = (v - sh_mu) * sh_rstd * g[tid] + b[tid];
    T[(size_t)row * WH + tid] = (y > 0.f) ? y : SLOPE * y;
}

// ================= bf16x3 tensor-core GEMM =================
__device__ __forceinline__ void ldsm4(unsigned* r, const __nv_bfloat16* p) {
    unsigned a = (unsigned)__cvta_generic_to_shared(p);
    asm volatile("ldmatrix.sync.aligned.m8n8.x4.shared.b16 {%0,%1,%2,%3}, [%4];"
                 : "=r"(r[0]), "=r"(r[1]), "=r"(r[2]), "=r"(r[3]) : "r"(a));
}
__device__ __forceinline__ void ldsm4t(unsigned* r, const __nv_bfloat16* p) {
    unsigned a = (unsigned)__cvta_generic_to_shared(p);
    asm volatile("ldmatrix.sync.aligned.m8n8.x4.trans.shared.b16 {%0,%1,%2,%3}, [%4];"
                 : "=r"(r[0]), "=r"(r[1]), "=r"(r[2]), "=r"(r[3]) : "r"(a));
}
__device__ __forceinline__ void mma_bf16(float* c, const unsigned* a, const unsigned* b) {
    asm volatile("mma.sync.aligned.m16n8k16.row.col.f32.bf16.bf16.f32 "
                 "{%0,%1,%2,%3}, {%4,%5,%6,%7}, {%8,%9}, {%0,%1,%2,%3};"
                 : "+f"(c[0]), "+f"(c[1]), "+f"(c[2]), "+f"(c[3])
                 : "r"(a[0]), "r"(a[1]), "r"(a[2]), "r"(a[3]), "r"(b[0]), "r"(b[1]));
}
__device__ __forceinline__ void split_bf16(float v, unsigned short& h, unsigned short& l) {
    __nv_bfloat16 hb = __float2bfloat16_rn(v);
    float res = v - __bfloat162float(hb);
    h = __bfloat16_as_ushort(hb);
    l = __bfloat16_as_ushort(__float2bfloat16_rn(res));
}

template <int BN, bool LEAKY>
__global__ __launch_bounds__(256, 2)
void bf16x3_gemm_kernel(int M, int K,
                        const float* __restrict__ A, int lda,
                        const float* __restrict__ B, int ldb,
                        const float* __restrict__ bias,
                        float* __restrict__ C, int ldc) {
    constexpr int NB8     = BN / 8;
    constexpr int WARPS_N = BN / 32;
    constexpr int WARPS_M = 8 / WARPS_N;
    constexpr int MT      = (128 / WARPS_M) / 16;
    constexpr int B_ITERS = BN / 64;
    constexpr int F4_ROW  = BN / 4;

    __shared__ __align__(16) __nv_bfloat16 Ah[128 * 16], Al[128 * 16];
    __shared__ __align__(16) __nv_bfloat16 Bh[16 * BN],  Bl[16 * BN];

    const int tid   = threadIdx.x;
    const int w     = tid >> 5;
    const int lane  = tid & 31;
    const int g     = lane >> 2;
    const int q     = lane & 3;
    const int warpN = (w % WARPS_N) * 32;
    const int warpM = (w / WARPS_N) * (MT * 16);
    const int brow  = blockIdx.x * 128;
    const int bcol  = blockIdx.y * BN;

    float acc[MT][4][4];
    #pragma unroll
    for (int mt = 0; mt < MT; mt++)
        #pragma unroll
        for (int nt = 0; nt < 4; nt++)
            #pragma unroll
            for (int i = 0; i < 4; i++) acc[mt][nt][i] = 0.f;

    float4 pa[2], pb[B_ITERS];

    auto load_tile = [&](int k0) {
        #pragma unroll
        for (int i = 0; i < 2; i++) {
            int idx = tid + i * 256;
            int r   = idx >> 2;
            int kq  = (idx & 3) * 4;
            pa[i] = (brow + r < M)
                  ? *(const float4*)(A + (size_t)(brow + r) * lda + k0 + kq)
                  : make_float4(0.f, 0.f, 0.f, 0.f);
        }
        #pragma unroll
        for (int i = 0; i < B_ITERS; i++) {
            int idx = tid + i * 256;
            int k   = idx / F4_ROW;
            int n4  = (idx % F4_ROW) * 4;
            pb[i] = *(const float4*)(B + (size_t)(k0 + k) * ldb + bcol + n4);
        }
    };
    auto store_tile = [&]() {
        #pragma unroll
        for (int i = 0; i < 2; i++) {
            int idx = tid + i * 256;
            int r   = idx >> 2;
            int kq  = (idx & 3) * 4;
            float vv[4] = {pa[i].x, pa[i].y, pa[i].z, pa[i].w};
            unsigned short h[4], l[4];
            #pragma unroll
            for (int j = 0; j < 4; j++) split_bf16(vv[j], h[j], l[j]);
            int ci = (r * 2 + ((kq >> 3) ^ ((r >> 2) & 1))) * 8 + (kq & 4);
            uint2 hp = make_uint2((unsigned)h[0] | ((unsigned)h[1] << 16),
                                  (unsigned)h[2] | ((unsigned)h[3] << 16));
            uint2 lp = make_uint2((unsigned)l[0] | ((unsigned)l[1] << 16),
                                  (unsigned)l[2] | ((unsigned)l[3] << 16));
            *(uint2*)&Ah[ci] = hp;
            *(uint2*)&Al[ci] = lp;
        }
        #pragma unroll
        for (int i = 0; i < B_ITERS; i++) {
            int idx = tid + i * 256;
            int k   = idx / F4_ROW;
            int n4  = (idx % F4_ROW) * 4;
            float vv[4] = {pb[i].x, pb[i].y, pb[i].z, pb[i].w};
            unsigned short h[4], l[4];
            #pragma unroll
            for (int j = 0; j < 4; j++) split_bf16(vv[j], h[j], l[j]);
            int ci = (k * NB8 + ((n4 >> 3) ^ (k & 7))) * 8 + (n4 & 4);
            uint2 hp = make_uint2((unsigned)h[0] | ((unsigned)h[1] << 16),
                                  (unsigned)h[2] | ((unsigned)h[3] << 16));
            uint2 lp = make_uint2((unsigned)l[0] | ((unsigned)l[1] << 16),
                                  (unsigned)l[2] | ((unsigned)l[3] << 16));
            *(uint2*)&Bh[ci] = hp;
            *(uint2*)&Bl[ci] = lp;
        }
    };

    load_tile(0);
    store_tile();
    __syncthreads();

    for (int k0 = 0; k0 < K; k0 += 16) {
        bool more = (k0 + 16) < K;
        if (more) load_tile(k0 + 16);

        unsigned bhf[4][2], blf[4][2];
        #pragma unroll
        for (int j = 0; j < 2; j++) {
            int k  = lane & 15;
            int n8 = ((warpN + j * 16) >> 3) + (lane >> 4);
            int ch = k * NB8 + (n8 ^ (k & 7));
            unsigned r4[4];
            ldsm4t(r4, &Bh[ch * 8]);
            bhf[2 * j][0] = r4[0]; bhf[2 * j][1] = r4[1];
            bhf[2 * j + 1][0] = r4[2]; bhf[2 * j + 1][1] = r4[3];
            ldsm4t(r4, &Bl[ch * 8]);
            blf[2 * j][0] = r4[0]; blf[2 * j][1] = r4[1];
            blf[2 * j + 1][0] = r4[2]; blf[2 * j + 1][1] = r4[3];
        }
        #pragma unroll
        for (int mt = 0; mt < MT; mt++) {
            int r  = warpM + mt * 16 + (lane & 15);
            int kh = lane >> 4;
            int ch = r * 2 + (kh ^ ((r >> 2) & 1));
            unsigned ah[4], al[4];
            ldsm4(ah, &Ah[ch * 8]);
            ldsm4(al, &Al[ch * 8]);
            #pragma unroll
            for (int nt = 0; nt < 4; nt++) {
                mma_bf16(acc[mt][nt], ah, bhf[nt]);
                mma_bf16(acc[mt][nt], ah, blf[nt]);
                mma_bf16(acc[mt][nt], al, bhf[nt]);
            }
        }
        __syncthreads();
        if (more) {
            store_tile();
            __syncthreads();
        }
    }

    #pragma unroll
    for (int nt = 0; nt < 4; nt++) {
        int gc = bcol + warpN + nt * 8 + 2 * q;
        float bx = bias[gc], by = bias[gc + 1];
        #pragma unroll
        for (int mt = 0; mt < MT; mt++) {
            int gr0 = brow + warpM + mt * 16 + g;
            float v0 = acc[mt][nt][0] + bx;
            float v1 = acc[mt][nt][1] + by;
            float v2 = acc[mt][nt][2] + bx;
            float v3 = acc[mt][nt][3] + by;
            if (LEAKY) {
                v0 = (v0 > 0.f) ? v0 : SLOPE * v0;
                v1 = (v1 > 0.f) ? v1 : SLOPE * v1;
                v2 = (v2 > 0.f) ? v2 : SLOPE * v2;
                v3 = (v3 > 0.f) ? v3 : SLOPE * v3;
            }
            if (gr0 < M)     *(float2*)(C + (size_t)gr0 * ldc + gc)       = make_float2(v0, v1);
            if (gr0 + 8 < M) *(float2*)(C + (size_t)(gr0 + 8) * ldc + gc) = make_float2(v2, v3);
        }
    }
}

// ---------------- launcher ----------------
extern "C" void kernel_launch(void* const* d_in, const int* in_sizes, int n_in,
                              void* d_out, int out_size) {
    const float* x      = (const float*)d_in[0];
    const void*  ei     = d_in[1];
    const float* ea     = (const float*)d_in[2];
    const float* in_W   = (const float*)d_in[3];
    const float* in_b   = (const float*)d_in[4];
    const float* eW     = (const float*)d_in[5];
    const float* eB     = (const float*)d_in[6];
    const float* W1     = (const float*)d_in[7];
    const float* b1     = (const float*)d_in[8];
    const float* ln_g   = (const float*)d_in[9];
    const float* ln_b   = (const float*)d_in[10];
    const float* W2     = (const float*)d_in[11];
    const float* b2     = (const float*)d_in[12];
    const float* W3     = (const float*)d_in[13];
    const float* b3     = (const float*)d_in[14];
    const float* out_W  = (const float*)d_in[15];
    const float* out_b  = (const float*)d_in[16];
    float* out = (float*)d_out;

    float* HID; cudaGetSymbolAddress((void**)&HID, g_HID);
    float* Z;   cudaGetSymbolAddress((void**)&Z,   g_Z);
    float* T1;  cudaGetSymbolAddress((void**)&T1,  g_T1);
    float* T2;  cudaGetSymbolAddress((void**)&T2,  g_T2);

    // 0) edge dtype detection + counting sort by dst (edges static across layers)
    detect_kernel<<<1, 1024>>>((const unsigned int*)ei);
    zero_kernel<<<(NN + 255) / 256, 256>>>();
    hist_kernel<<<(EE + 255) / 256, 256>>>(ei);
    scan_kernel<<<1, 1024>>>();
    scatter_kernel<<<(EE + 255) / 256, 256>>>(ei, ea);

    // 1) h0 = x @ in_W + in_b  -> HID[:, 0:128]
    bf16x3_gemm_kernel<64, false><<<dim3(79, 2), 256>>>(
        NN, 128, x, D_IN, in_W, HH, in_b, HID, 512);

    // 2) GINE layers
    for (int l = 0; l < LL; l++) {
        int hid_off = l * HH;
        const float* eWl = eW + l * D_CAT;
        const float* eBl = eB + l * D_CAT;
        const float* W1l = W1 + (size_t)l * D_CAT * WH;
        const float* b1l = b1 + l * WH;
        const float* gl  = ln_g + l * WH;
        const float* bbl = ln_b + l * WH;
        const float* W2l = W2 + (size_t)l * WH * WH;
        const float* b2l = b2 + l * WH;
        const float* W3l = W3 + (size_t)l * WH * HH;
        const float* b3l = b3 + l * HH;

        // Z = xc + segment_sum(relu(xc[src] + ea*eW + eB), dst)  (atomic-free)
        agg_z_kernel<<<(NN + 3) / 4, 256>>>(x, eWl, eBl, hid_off);
        // T1 = Z @ W1 + b1
        bf16x3_gemm_kernel<128, false><<<dim3(79, 2), 256>>>(
            NN, D_CAT, Z, D_CAT, W1l, WH, b1l, T1, WH);
        ln_leaky_kernel<<<NN, 256>>>(T1, gl, bbl);
        // T2 = leaky(T1 @ W2 + b2)
        bf16x3_gemm_kernel<128, true><<<dim3(79, 2), 256>>>(
            NN, WH, T1, WH, W2l, WH, b2l, T2, WH);
        // h_{l+1} = T2 @ W3 + b3
        bf16x3_gemm_kernel<64, false><<<dim3(79, 2), 256>>>(
            NN, WH, T2, WH, W3l, HH, b3l, HID + (l + 1) * HH, 512);
    }

    // 3) out = HID @ out_W + out_b
    bf16x3_gemm_kernel<64, false><<<dim3(79, 2), 256>>>(
        NN, 512, HID, 512, out_W, D_OUT, out_b, out, D_OUT);

    (void)in_sizes; (void)n_in; (void)out_size;
}